// round 5
// baseline (speedup 1.0000x reference)
#include <cuda_runtime.h>
#include <cstdint>

// ---------------- problem constants ----------------
#define DIMV   96
#define PVOX   (96*96*96)            // 884736 positions
#define CCH    32
#define NB     2
#define NPERB  30000
#define NVTOT  60000
#define VPG    16                    // vertices per group
#define NGROUPS (NVTOT/VPG)          // 3750
#define NPAIRS  152                  // block pairs (GB300 SMs)

// per-half (16 input channels) conv geometry
#define CHALF   16
#define ILOC    (CHALF*27)           // 432 reduction elems per half
#define I4LOC   (ILOC/4)             // 108
#define I4PADL  112                  // pad -> 14 i4-groups per warp * 8 warps
#define TPW     (I4PADL/8)           // 14
#define FSTR    464                  // feats row stride (16B-mult, ==16 mod 32 banks)

#define WQ_FLOATS   (I4PADL*32*4)    // 14336  (57344 B)
#define FS_FLOATS   (VPG*FSTR)       // 7424   (29696 B)
#define PART_FLOATS (8*VPG*32)       // 4096   (16384 B)
#define SMEM_FLOATS (WQ_FLOATS+FS_FLOATS+PART_FLOATS)
#define SMEM_BYTES  (SMEM_FLOATS*4)  // 103424 B per block -> 2 blocks/SM

// ---------------- static scratch ----------------
__device__ float g_vt[(size_t)NB * PVOX * CCH];     // (B,H,W,D,C)
__device__ float g_pb[(size_t)2 * NVTOT * 32];      // per-half partial outputs

// Packed fp32x2 FMA (Blackwell)
static __device__ __forceinline__ unsigned long long ffma2(
    unsigned long long a, unsigned long long b, unsigned long long c) {
    unsigned long long d;
    asm("fma.rn.f32x2 %0, %1, %2, %3;" : "=l"(d) : "l"(a), "l"(b), "l"(c));
    return d;
}
static __device__ __forceinline__ void unpack2(unsigned long long v, float& x, float& y) {
    asm("mov.b64 {%0, %1}, %2;" : "=f"(x), "=f"(y) : "l"(v));
}

// ---------------------------------------------------------------------------
// Kernel 1: transpose (B,C,P) -> (B,P,C); 32c x 128p tiles, float4 both sides
// ---------------------------------------------------------------------------
__global__ void __launch_bounds__(256) transpose_kernel(
    const float* __restrict__ in, float* __restrict__ vt) {
    __shared__ float tile[32][128];
    const int b  = blockIdx.y;
    const int p0 = blockIdx.x * 128;
    const int tid = threadIdx.x;

    const float* ib = in + (size_t)b * CCH * PVOX;
#pragma unroll
    for (int it = 0; it < 4; it++) {
        int g = it * 256 + tid;          // 0..1023
        int c = g >> 5, j = g & 31;      // j = float4 idx along p
        float4 v = *reinterpret_cast<const float4*>(ib + (size_t)c * PVOX + p0 + j * 4);
        *reinterpret_cast<float4*>(&tile[c][j * 4]) = v;
    }
    __syncthreads();
    float* ob = vt + ((size_t)b * PVOX + p0) * CCH;
#pragma unroll
    for (int it = 0; it < 4; it++) {
        int g  = it * 256 + tid;
        int p  = g & 127, cg = g >> 7;   // cg 0..7
        float4 v = make_float4(tile[cg * 4 + 0][p], tile[cg * 4 + 1][p],
                               tile[cg * 4 + 2][p], tile[cg * 4 + 3][p]);
        *reinterpret_cast<float4*>(ob + (size_t)p * CCH + cg * 4) = v;
    }
}

// ---------------------------------------------------------------------------
// Kernel 2: fused sample+conv, channel-split halves, 2 blocks/SM.
//  Block pair (2g, 2g+1): same 16 vertices, input channels [0,16) / [16,32).
//  Phase 1: warp = 2 vertices x 16 channels (half-warps), separable trilinear
//           over clamped 4x4x4 window -> smem feats [v][FSTR].
//  Phase 2: lane = out channel, warp w covers i4 in [14w,14w+14) for all 16 v
//           (W amortized 16x), packed f32x2 FMA.
//  Phase 3: reduce 8 warp partials -> g_pb[half].
// ---------------------------------------------------------------------------
__global__ void __launch_bounds__(256, 2) fused_kernel(
    const float* __restrict__ vt,
    const float* __restrict__ verts,
    const float* __restrict__ Wg,        // (32,32,1,27): o*864 + c*27 + k
    float* __restrict__ pb) {
    extern __shared__ float sm[];
    float* Wq   = sm;                         // [I4PADL][32][4]
    float* fs   = sm + WQ_FLOATS;             // [VPG][FSTR]
    float* part = sm + WQ_FLOATS + FS_FLOATS; // [8][VPG][32]

    const int tid  = threadIdx.x;
    const int warp = tid >> 5;
    const int lane = tid & 31;
    const int half = blockIdx.x & 1;          // channel half
    const int pair = blockIdx.x >> 1;

    // one-time: stage W half into smem (vector layout), zero i4 pads
    for (int g = tid; g < 32 * I4PADL; g += 256) {
        int o  = g / I4PADL;
        int i4 = g - o * I4PADL;
        float4 w = make_float4(0.f, 0.f, 0.f, 0.f);
        if (i4 < I4LOC)
            w = *reinterpret_cast<const float4*>(Wg + (size_t)o * 864 + half * ILOC + i4 * 4);
        *reinterpret_cast<float4*>(Wq + ((size_t)i4 * 32 + o) * 4) = w;
    }
    // zero feats pad region [432,448) for each vertex slot
    {
        int v = tid >> 4, j = tid & 15;   // 256 threads = 16 v x 16 j
        fs[v * FSTR + ILOC + j] = 0.f;
    }
    __syncthreads();

    const int v2 = lane >> 4;          // vertex within warp
    const int cl = lane & 15;          // local channel

    for (int grp = pair; grp < NGROUPS; grp += NPAIRS) {
        const int vloc  = warp * 2 + v2;
        const int vglob = grp * VPG + vloc;
        const int b = vglob / NPERB;

        // ============== Phase 1: separable trilinear ==============
        const float vx = verts[(size_t)vglob * 3 + 0];  // -> D axis
        const float vy = verts[(size_t)vglob * 3 + 1];  // -> W axis
        const float vz = verts[(size_t)vglob * 3 + 2];  // -> H axis

        float fx, fy, fz;
        int xo[4], yo[4], zo[4];
        {
            float f = fminf(fmaxf((vx + 1.f) * (0.5f * 95.f), 0.f), 95.f);
            int i0 = (int)f; fx = f - (float)i0;
#pragma unroll
            for (int j = 0; j < 4; j++) xo[j] = min(max(i0 - 1 + j, 0), 95) * CCH;
        }
        {
            float f = fminf(fmaxf((vy + 1.f) * (0.5f * 95.f), 0.f), 95.f);
            int i0 = (int)f; fy = f - (float)i0;
#pragma unroll
            for (int j = 0; j < 4; j++) yo[j] = min(max(i0 - 1 + j, 0), 95) * (DIMV * CCH);
        }
        {
            float f = fminf(fmaxf((vz + 1.f) * (0.5f * 95.f), 0.f), 95.f);
            int i0 = (int)f; fz = f - (float)i0;
#pragma unroll
            for (int j = 0; j < 4; j++) zo[j] = min(max(i0 - 1 + j, 0), 95) * (DIMV * DIMV * CCH);
        }
        const float omfz = 1.f - fz;
        const float* bp = vt + (size_t)b * ((size_t)PVOX * CCH) + half * CHALF + cl;

        float acc[27];
#pragma unroll
        for (int kk = 0; kk < 27; kk++) acc[kk] = 0.f;

#pragma unroll
        for (int jz = 0; jz < 4; jz++) {
            float t4[12];
#pragma unroll
            for (int jy = 0; jy < 4; jy++) {
                const float* r = bp + zo[jz] + yo[jy];
                float a0 = __ldg(r + xo[0]);
                float a1 = __ldg(r + xo[1]);
                float a2 = __ldg(r + xo[2]);
                float a3 = __ldg(r + xo[3]);
                t4[jy * 3 + 0] = a0 + fx * (a1 - a0);
                t4[jy * 3 + 1] = a1 + fx * (a2 - a1);
                t4[jy * 3 + 2] = a2 + fx * (a3 - a2);
            }
#pragma unroll
            for (int dy = 0; dy < 3; dy++) {
#pragma unroll
                for (int dxx = 0; dxx < 3; dxx++) {
                    float a  = t4[dy * 3 + dxx];
                    float bq = t4[(dy + 1) * 3 + dxx];
                    float ly = a + fy * (bq - a);
                    if (jz < 3) acc[dxx * 9 + dy * 3 + jz]       += omfz * ly;
                    if (jz > 0) acc[dxx * 9 + dy * 3 + (jz - 1)] += fz   * ly;
                }
            }
        }
        {
            float* fr = fs + vloc * FSTR + cl * 27;   // i_local = cl*27 + k
#pragma unroll
            for (int kk = 0; kk < 27; kk++) fr[kk] = acc[kk];
        }
        __syncthreads();

        // ============== Phase 2: conv (lane = out channel) ==============
        {
            unsigned long long acc2[VPG];
#pragma unroll
            for (int v = 0; v < VPG; v++) acc2[v] = 0ull;

            const int i4base = warp * TPW;
            for (int t = 0; t < TPW; t++) {
                const int i4 = i4base + t;
                ulonglong2 w2 = *reinterpret_cast<const ulonglong2*>(
                    Wq + ((size_t)i4 * 32 + lane) * 4);
#pragma unroll
                for (int v = 0; v < VPG; v++) {
                    ulonglong2 f2 = *reinterpret_cast<const ulonglong2*>(
                        fs + (size_t)v * FSTR + i4 * 4);
                    acc2[v] = ffma2(w2.x, f2.x, acc2[v]);
                    acc2[v] = ffma2(w2.y, f2.y, acc2[v]);
                }
            }
#pragma unroll
            for (int v = 0; v < VPG; v++) {
                float x, y; unpack2(acc2[v], x, y);
                part[((size_t)warp * VPG + v) * 32 + lane] = x + y;
            }
        }
        __syncthreads();

        // ============== Phase 3: reduce + store half-partial ==============
#pragma unroll
        for (int vi = 0; vi < 2; vi++) {
            int vv = warp * 2 + vi;
            float s = 0.f;
#pragma unroll
            for (int w2 = 0; w2 < 8; w2++)
                s += part[((size_t)w2 * VPG + vv) * 32 + lane];
            pb[((size_t)half * NVTOT + grp * VPG + vv) * 32 + lane] = s;
        }
        __syncthreads();   // protect part/fs before next group
    }
}

// ---------------------------------------------------------------------------
// Kernel 3: out = bias + pb[half0] + pb[half1]   (float4)
// ---------------------------------------------------------------------------
__global__ void __launch_bounds__(256) add_kernel(
    const float* __restrict__ pb, const float* __restrict__ bias,
    float* __restrict__ out) {
    int i4 = blockIdx.x * 256 + threadIdx.x;        // float4 index
    if (i4 >= NVTOT * 32 / 4) return;
    int c0 = (i4 * 4) & 31;
    float4 bs = *reinterpret_cast<const float4*>(bias + c0);
    float4 a  = *reinterpret_cast<const float4*>(pb + (size_t)i4 * 4);
    float4 bq = *reinterpret_cast<const float4*>(pb + (size_t)NVTOT * 32 + (size_t)i4 * 4);
    float4 r = make_float4(bs.x + a.x + bq.x, bs.y + a.y + bq.y,
                           bs.z + a.z + bq.z, bs.w + a.w + bq.w);
    *reinterpret_cast<float4*>(out + (size_t)i4 * 4) = r;
}

// ---------------------------------------------------------------------------
extern "C" void kernel_launch(void* const* d_in, const int* in_sizes, int n_in,
                              void* d_out, int out_size) {
    const float* vox   = (const float*)d_in[0];   // (2,32,96,96,96)
    const float* verts = (const float*)d_in[1];   // (2,30000,3)
    const float* Wg    = (const float*)d_in[2];   // (32,32,1,27)
    const float* bias  = (const float*)d_in[3];   // (32,)
    float* out = (float*)d_out;

    float *vt = nullptr, *pb = nullptr;
    cudaGetSymbolAddress((void**)&vt, g_vt);
    cudaGetSymbolAddress((void**)&pb, g_pb);

    cudaFuncSetAttribute(fused_kernel,
                         cudaFuncAttributeMaxDynamicSharedMemorySize, SMEM_BYTES);

    transpose_kernel<<<dim3(PVOX / 128, NB), 256>>>(vox, vt);
    fused_kernel<<<2 * NPAIRS, 256, SMEM_BYTES>>>(vt, verts, Wg, pb);
    add_kernel<<<(NVTOT * 32 / 4 + 255) / 256, 256>>>(pb, bias, out);
}

// round 6
// speedup vs baseline: 1.8924x; 1.8924x over previous
#include <cuda_runtime.h>
#include <cuda_fp16.h>
#include <cstdint>

// ---------------- problem constants ----------------
#define DIMV   96
#define PVOX   (96*96*96)            // 884736 positions
#define CCH    32
#define NB     2
#define NPERB  30000
#define NVTOT  60000
#define VPB    16                    // vertices per group (= warps per block)
#define NGROUPS (NVTOT/VPB)          // 3750
#define ITOT   864                   // C*27
#define I4TOT  216
#define I4PAD  224                   // 14 i4-groups per warp * 16 warps
#define FSTRIDE 896                  // padded feats row

#define WQ_FLOATS  (I4PAD*32*4)      // 28672 floats (114688 B)
#define FS_FLOATS  (VPB*FSTRIDE)     // 14336 floats (57344 B)
#define PART_FLOATS (16*VPB*32)      // 8192 floats (32768 B)
#define SMEM_FLOATS (WQ_FLOATS+FS_FLOATS+PART_FLOATS)
#define SMEM_BYTES  (SMEM_FLOATS*4)  // 204800 B

// Scratch: transposed voxel features (B, H, W, D, C) in fp16 (113 MB -> L2-resident)
__device__ __half g_vt[(size_t)NB * PVOX * CCH];

// Packed fp32x2 FMA (Blackwell)
static __device__ __forceinline__ unsigned long long ffma2(
    unsigned long long a, unsigned long long b, unsigned long long c) {
    unsigned long long d;
    asm("fma.rn.f32x2 %0, %1, %2, %3;" : "=l"(d) : "l"(a), "l"(b), "l"(c));
    return d;
}
static __device__ __forceinline__ void unpack2(unsigned long long v, float& x, float& y) {
    asm("mov.b64 {%0, %1}, %2;" : "=f"(x), "=f"(y) : "l"(v));
}

// ---------------------------------------------------------------------------
// Kernel 1: transpose (B,C,P) fp32 -> (B,P,C) fp16, pure register transpose.
//  Warp handles 32 positions: lane l owns position p0+l. 32 coalesced LDG.32
//  (one per channel, 128B/instr), convert to 16 half2, 4x STG.128 per lane
//  (contiguous 64B per position). MLP=32.
// ---------------------------------------------------------------------------
__global__ void __launch_bounds__(256) transpose_kernel(
    const float* __restrict__ in, __half* __restrict__ vt) {
    const int b    = blockIdx.y;
    const int warp = threadIdx.x >> 5;
    const int lane = threadIdx.x & 31;
    const int p0   = (blockIdx.x * 8 + warp) * 32;

    const float* ib = in + (size_t)b * CCH * PVOX + p0 + lane;
    __half2 h[16];
#pragma unroll
    for (int c = 0; c < 32; c += 2) {
        float v0 = __ldg(ib + (size_t)c * PVOX);
        float v1 = __ldg(ib + (size_t)(c + 1) * PVOX);
        h[c >> 1] = __floats2half2_rn(v0, v1);
    }
    uint4* ob = reinterpret_cast<uint4*>(vt + ((size_t)b * PVOX + p0 + lane) * CCH);
    const uint4* hs = reinterpret_cast<const uint4*>(h);
#pragma unroll
    for (int k = 0; k < 4; k++) ob[k] = hs[k];
}

// ---------------------------------------------------------------------------
// Kernel 2: persistent fused sample + conv (round-4 structure, fp16 gather).
//  Block = 512 threads = 16 warps; group = 16 vertices.
//  Phase 1: warp-per-vertex separable trilinear over clamped 4x4x4 window,
//           lane = input channel (fp16 loads, fp32 math); feats -> smem.
//  Phase 2: lane = output channel; warp w covers 14 i4-groups for ALL 16
//           vertices (W smem amortized 16x); packed f32x2 FMA.
//  Phase 3: cross-warp reduction + bias, coalesced store.
// ---------------------------------------------------------------------------
__global__ void __launch_bounds__(512, 1) fused_kernel(
    const __half* __restrict__ vt,
    const float* __restrict__ verts,
    const float* __restrict__ Wg,      // (32,32,1,27) -> o*864 + c*27 + k
    const float* __restrict__ bias,
    float* __restrict__ out) {
    extern __shared__ float sm[];
    float* Wq   = sm;                         // [I4PAD][32][4]
    float* fs   = sm + WQ_FLOATS;             // [VPB][FSTRIDE]
    float* part = sm + WQ_FLOATS + FS_FLOATS; // [16][VPB][32]

    const int tid  = threadIdx.x;
    const int warp = tid >> 5;
    const int lane = tid & 31;

    // one-time: stage W into smem (vector layout), zero pads
    for (int g = tid; g < 32 * I4PAD; g += 512) {
        int o  = g / I4PAD;
        int i4 = g - o * I4PAD;
        float4 w = make_float4(0.f, 0.f, 0.f, 0.f);
        if (i4 < I4TOT) w = *reinterpret_cast<const float4*>(Wg + (size_t)o * ITOT + i4 * 4);
        *reinterpret_cast<float4*>(Wq + ((size_t)i4 * 32 + o) * 4) = w;
    }
    {   // zero feats tail [864,896) per vertex slot
        int v = tid >> 5;
        fs[v * FSTRIDE + ITOT + lane] = 0.f;
    }
    __syncthreads();

    for (int grp = blockIdx.x; grp < NGROUPS; grp += gridDim.x) {
        const int vglob = grp * VPB + warp;
        const int b = vglob / NPERB;
        const int n = vglob - b * NPERB;

        // ================= Phase 1: separable trilinear =====================
        const float vx = verts[(size_t)vglob * 3 + 0];  // -> D axis
        const float vy = verts[(size_t)vglob * 3 + 1];  // -> W axis
        const float vz = verts[(size_t)vglob * 3 + 2];  // -> H axis

        float fx, fy, fz;
        int xo[4], yo[4], zo[4];
        {
            float f = fminf(fmaxf((vx + 1.f) * (0.5f * 95.f), 0.f), 95.f);
            int i0 = (int)f; fx = f - (float)i0;
#pragma unroll
            for (int j = 0; j < 4; j++) xo[j] = min(max(i0 - 1 + j, 0), 95) * CCH;
        }
        {
            float f = fminf(fmaxf((vy + 1.f) * (0.5f * 95.f), 0.f), 95.f);
            int i0 = (int)f; fy = f - (float)i0;
#pragma unroll
            for (int j = 0; j < 4; j++) yo[j] = min(max(i0 - 1 + j, 0), 95) * (DIMV * CCH);
        }
        {
            float f = fminf(fmaxf((vz + 1.f) * (0.5f * 95.f), 0.f), 95.f);
            int i0 = (int)f; fz = f - (float)i0;
#pragma unroll
            for (int j = 0; j < 4; j++) zo[j] = min(max(i0 - 1 + j, 0), 95) * (DIMV * DIMV * CCH);
        }
        const float omfz = 1.f - fz;
        const __half* bp = vt + (size_t)b * ((size_t)PVOX * CCH) + lane;

        float acc[27];
#pragma unroll
        for (int kk = 0; kk < 27; kk++) acc[kk] = 0.f;

#pragma unroll
        for (int jz = 0; jz < 4; jz++) {
            float t4[12];
#pragma unroll
            for (int jy = 0; jy < 4; jy++) {
                const __half* r = bp + zo[jz] + yo[jy];
                float a0 = __half2float(__ldg(r + xo[0]));
                float a1 = __half2float(__ldg(r + xo[1]));
                float a2 = __half2float(__ldg(r + xo[2]));
                float a3 = __half2float(__ldg(r + xo[3]));
                t4[jy * 3 + 0] = a0 + fx * (a1 - a0);
                t4[jy * 3 + 1] = a1 + fx * (a2 - a1);
                t4[jy * 3 + 2] = a2 + fx * (a3 - a2);
            }
#pragma unroll
            for (int dy = 0; dy < 3; dy++) {
#pragma unroll
                for (int dxx = 0; dxx < 3; dxx++) {
                    float a  = t4[dy * 3 + dxx];
                    float bq = t4[(dy + 1) * 3 + dxx];
                    float ly = a + fy * (bq - a);
                    if (jz < 3) acc[dxx * 9 + dy * 3 + jz]       += omfz * ly;
                    if (jz > 0) acc[dxx * 9 + dy * 3 + (jz - 1)] += fz   * ly;
                }
            }
        }
        {
            float* fr = fs + warp * FSTRIDE + lane * 27;  // i = c*27 + k
#pragma unroll
            for (int kk = 0; kk < 27; kk++) fr[kk] = acc[kk];
        }
        __syncthreads();

        // ================= Phase 2: conv, lane = output channel =============
        {
            unsigned long long acc2[VPB];
#pragma unroll
            for (int v = 0; v < VPB; v++) acc2[v] = 0ull;

            const int i4base = warp * (I4PAD / 16);   // 14 per warp
            for (int t = 0; t < I4PAD / 16; t++) {
                const int i4 = i4base + t;
                ulonglong2 w2 = *reinterpret_cast<const ulonglong2*>(
                    Wq + ((size_t)i4 * 32 + lane) * 4);
#pragma unroll
                for (int v = 0; v < VPB; v++) {
                    ulonglong2 f2v = *reinterpret_cast<const ulonglong2*>(
                        fs + (size_t)v * FSTRIDE + i4 * 4);
                    acc2[v] = ffma2(w2.x, f2v.x, acc2[v]);
                    acc2[v] = ffma2(w2.y, f2v.y, acc2[v]);
                }
            }
#pragma unroll
            for (int v = 0; v < VPB; v++) {
                float x, y; unpack2(acc2[v], x, y);
                part[((size_t)warp * VPB + v) * 32 + lane] = x + y;
            }
        }
        __syncthreads();

        // ================= Phase 3: reduce + bias, store ====================
        {
            float s = __ldg(bias + lane);
#pragma unroll
            for (int w2 = 0; w2 < 16; w2++)
                s += part[((size_t)w2 * VPB + warp) * 32 + lane];
            out[((size_t)b * NPERB + n) * 32 + lane] = s;
        }
        __syncthreads();  // protect part/fs before next group
    }
}

// ---------------------------------------------------------------------------
extern "C" void kernel_launch(void* const* d_in, const int* in_sizes, int n_in,
                              void* d_out, int out_size) {
    const float* vox   = (const float*)d_in[0];   // (2,32,96,96,96)
    const float* verts = (const float*)d_in[1];   // (2,30000,3)
    const float* Wg    = (const float*)d_in[2];   // (32,32,1,27)
    const float* bias  = (const float*)d_in[3];   // (32,)
    float* out = (float*)d_out;

    __half* vt = nullptr;
    cudaGetSymbolAddress((void**)&vt, g_vt);

    cudaFuncSetAttribute(fused_kernel,
                         cudaFuncAttributeMaxDynamicSharedMemorySize, SMEM_BYTES);

    transpose_kernel<<<dim3(PVOX / 256, NB), 256>>>(vox, vt);
    fused_kernel<<<152, 512, SMEM_BYTES>>>(vt, verts, Wg, bias, out);
}

// round 7
// speedup vs baseline: 3.0107x; 1.5909x over previous
#include <cuda_runtime.h>
#include <cuda_fp16.h>
#include <cstdint>

// ---------------- problem constants ----------------
#define DIMV   96
#define PVOX   (96*96*96)            // 884736 positions
#define CCH    32
#define NB     2
#define NPERB  30000
#define NVTOT  60000
#define VPB    16                    // vertices per group (= warps per block)
#define NGROUPS (NVTOT/VPB)          // 3750
#define ITOT   864                   // C*27 reduction length
#define KPAD   1024                  // padded K (64 k16-steps, 4 per warp)

// smem layout (bytes). Row strides are 2064 B == 16 mod 128 -> conflict-free
// fragment loads (bank = 4*(l/4) + (l%4), a permutation of 0..31).
#define WSTRB  2064                  // W row (o-major, k contiguous, fp16)
#define FSTRB  2064                  // feats row (v-major, k contiguous, fp16)
#define WH_BYTES (32*WSTRB)          // 66048
#define FS_BYTES (VPB*FSTRB)         // 33024
#define OSTR   36                    // part row stride (floats), ==4 mod 32
#define PARTW  (16*OSTR)             // floats per warp slab (576)
#define PART_BYTES (16*PARTW*4)      // 36864
#define SMEM_BYTES (WH_BYTES + FS_BYTES + PART_BYTES)   // 135936

// Scratch: transposed voxel features (B,H,W,D,C) fp16 (113 MB -> L2-resident)
__device__ __half g_vt[(size_t)NB * PVOX * CCH];

// warp MMA m16n8k16 f16 x f16 -> f32
static __device__ __forceinline__ void mma16816(
    float& c0, float& c1, float& c2, float& c3,
    uint32_t a0, uint32_t a1, uint32_t a2, uint32_t a3,
    uint32_t b0, uint32_t b1) {
    asm volatile(
        "mma.sync.aligned.m16n8k16.row.col.f32.f16.f16.f32 "
        "{%0,%1,%2,%3}, {%4,%5,%6,%7}, {%8,%9}, {%0,%1,%2,%3};"
        : "+f"(c0), "+f"(c1), "+f"(c2), "+f"(c3)
        : "r"(a0), "r"(a1), "r"(a2), "r"(a3), "r"(b0), "r"(b1));
}

// ---------------------------------------------------------------------------
// Kernel 1: transpose (B,C,P) fp32 -> (B,P,C) fp16, register transpose.
// ---------------------------------------------------------------------------
__global__ void __launch_bounds__(256) transpose_kernel(
    const float* __restrict__ in, __half* __restrict__ vt) {
    const int b    = blockIdx.y;
    const int warp = threadIdx.x >> 5;
    const int lane = threadIdx.x & 31;
    const int p0   = (blockIdx.x * 8 + warp) * 32;

    const float* ib = in + (size_t)b * CCH * PVOX + p0 + lane;
    __half2 h[16];
#pragma unroll
    for (int c = 0; c < 32; c += 2) {
        float v0 = __ldg(ib + (size_t)c * PVOX);
        float v1 = __ldg(ib + (size_t)(c + 1) * PVOX);
        h[c >> 1] = __floats2half2_rn(v0, v1);
    }
    uint4* ob = reinterpret_cast<uint4*>(vt + ((size_t)b * PVOX + p0 + lane) * CCH);
    const uint4* hs = reinterpret_cast<const uint4*>(h);
#pragma unroll
    for (int k = 0; k < 4; k++) ob[k] = hs[k];
}

// ---------------------------------------------------------------------------
// Kernel 2: persistent fused sample + conv (conv via warp HMMA).
//  Block = 512 thr = 16 warps; group = 16 vertices.
//  Phase 1: warp-per-vertex separable trilinear over clamped 4x4x4 window,
//           lane = input channel; feats -> smem fp16 [v][k=c*27+tap].
//  Phase 2: warp w covers k16-steps [4w,4w+4) for all 16 v x 32 o via
//           mma.sync m16n8k16 (A=feats frag, B=W frag), fp32 accum.
//  Phase 3: cross-warp reduce 16 partials + bias, coalesced store.
// ---------------------------------------------------------------------------
__global__ void __launch_bounds__(512, 1) fused_kernel(
    const __half* __restrict__ vt,
    const float* __restrict__ verts,
    const float* __restrict__ Wg,      // (32,32,1,27): o*864 + c*27 + k
    const float* __restrict__ bias,
    float* __restrict__ out) {
    extern __shared__ char smc[];
    char*  smw  = smc;                       // W fp16 [32][WSTRB]
    char*  smf  = smc + WH_BYTES;            // feats fp16 [16][FSTRB]
    float* part = (float*)(smc + WH_BYTES + FS_BYTES); // [16 warps][16 v][OSTR]

    const int tid  = threadIdx.x;
    const int warp = tid >> 5;
    const int lane = tid & 31;

    // ---- one-time: stage W (fp16, o-major), zero K-pad; zero feats pad ----
    for (int g = tid; g < 32 * (WSTRB / 4); g += 512) {   // word granularity
        int o = g / (WSTRB / 4);
        int w = g - o * (WSTRB / 4);
        int k0 = w * 2;
        __half2 hv = __floats2half2_rn(0.f, 0.f);
        if (k0 < ITOT) {
            float w0 = Wg[(size_t)o * ITOT + k0];
            float w1 = (k0 + 1 < ITOT) ? Wg[(size_t)o * ITOT + k0 + 1] : 0.f;
            hv = __floats2half2_rn(w0, w1);
        }
        *reinterpret_cast<uint32_t*>(smw + (size_t)o * WSTRB + w * 4) =
            *reinterpret_cast<uint32_t*>(&hv);
    }
    // feats: zero words [ITOT/2, FSTRB/4) of every vertex row (pad, never rewritten)
    for (int g = tid; g < VPB * (FSTRB / 4 - ITOT / 2); g += 512) {
        int v = g / (FSTRB / 4 - ITOT / 2);
        int j = g - v * (FSTRB / 4 - ITOT / 2) + ITOT / 2;
        *reinterpret_cast<uint32_t*>(smf + (size_t)v * FSTRB + j * 4) = 0u;
    }
    __syncthreads();

    const int gq = lane >> 2;   // l/4 : fragment row
    const int qq = lane & 3;    // l%4 : fragment col group

    for (int grp = blockIdx.x; grp < NGROUPS; grp += gridDim.x) {
        const int vglob = grp * VPB + warp;
        const int b = vglob / NPERB;
        const int n = vglob - b * NPERB;

        // ================= Phase 1: separable trilinear =====================
        const float vx = verts[(size_t)vglob * 3 + 0];  // -> D axis
        const float vy = verts[(size_t)vglob * 3 + 1];  // -> W axis
        const float vz = verts[(size_t)vglob * 3 + 2];  // -> H axis

        float fx, fy, fz;
        int xo[4], yo[4], zo[4];
        {
            float f = fminf(fmaxf((vx + 1.f) * (0.5f * 95.f), 0.f), 95.f);
            int i0 = (int)f; fx = f - (float)i0;
#pragma unroll
            for (int j = 0; j < 4; j++) xo[j] = min(max(i0 - 1 + j, 0), 95) * CCH;
        }
        {
            float f = fminf(fmaxf((vy + 1.f) * (0.5f * 95.f), 0.f), 95.f);
            int i0 = (int)f; fy = f - (float)i0;
#pragma unroll
            for (int j = 0; j < 4; j++) yo[j] = min(max(i0 - 1 + j, 0), 95) * (DIMV * CCH);
        }
        {
            float f = fminf(fmaxf((vz + 1.f) * (0.5f * 95.f), 0.f), 95.f);
            int i0 = (int)f; fz = f - (float)i0;
#pragma unroll
            for (int j = 0; j < 4; j++) zo[j] = min(max(i0 - 1 + j, 0), 95) * (DIMV * DIMV * CCH);
        }
        const float omfz = 1.f - fz;
        const __half* bp = vt + (size_t)b * ((size_t)PVOX * CCH) + lane;

        float acc[27];
#pragma unroll
        for (int kk = 0; kk < 27; kk++) acc[kk] = 0.f;

#pragma unroll
        for (int jz = 0; jz < 4; jz++) {
            float t4[12];
#pragma unroll
            for (int jy = 0; jy < 4; jy++) {
                const __half* r = bp + zo[jz] + yo[jy];
                float a0 = __half2float(__ldg(r + xo[0]));
                float a1 = __half2float(__ldg(r + xo[1]));
                float a2 = __half2float(__ldg(r + xo[2]));
                float a3 = __half2float(__ldg(r + xo[3]));
                t4[jy * 3 + 0] = a0 + fx * (a1 - a0);
                t4[jy * 3 + 1] = a1 + fx * (a2 - a1);
                t4[jy * 3 + 2] = a2 + fx * (a3 - a2);
            }
#pragma unroll
            for (int dy = 0; dy < 3; dy++) {
#pragma unroll
                for (int dxx = 0; dxx < 3; dxx++) {
                    float a  = t4[dy * 3 + dxx];
                    float bq = t4[(dy + 1) * 3 + dxx];
                    float ly = a + fy * (bq - a);
                    if (jz < 3) acc[dxx * 9 + dy * 3 + jz]       += omfz * ly;
                    if (jz > 0) acc[dxx * 9 + dy * 3 + (jz - 1)] += fz   * ly;
                }
            }
        }
        {   // feats[v=warp][k = lane*27 + kk] as fp16
            __half* fr = reinterpret_cast<__half*>(smf + (size_t)warp * FSTRB) + lane * 27;
#pragma unroll
            for (int kk = 0; kk < 27; kk++) fr[kk] = __float2half_rn(acc[kk]);
        }
        __syncthreads();

        // ================= Phase 2: HMMA conv ===============================
        {
            float c[4][4];
#pragma unroll
            for (int nt = 0; nt < 4; nt++)
#pragma unroll
                for (int r = 0; r < 4; r++) c[nt][r] = 0.f;

#pragma unroll
            for (int t = 0; t < 4; t++) {
                const int kb = (warp * 4 + t) * 32;   // byte offset of k-step
                uint32_t a0 = *reinterpret_cast<const uint32_t*>(
                    smf + (size_t)gq * FSTRB + kb + qq * 4);
                uint32_t a1 = *reinterpret_cast<const uint32_t*>(
                    smf + (size_t)(gq + 8) * FSTRB + kb + qq * 4);
                uint32_t a2 = *reinterpret_cast<const uint32_t*>(
                    smf + (size_t)gq * FSTRB + kb + 16 + qq * 4);
                uint32_t a3 = *reinterpret_cast<const uint32_t*>(
                    smf + (size_t)(gq + 8) * FSTRB + kb + 16 + qq * 4);
#pragma unroll
                for (int nt = 0; nt < 4; nt++) {
                    const int o = nt * 8 + gq;
                    uint32_t b0 = *reinterpret_cast<const uint32_t*>(
                        smw + (size_t)o * WSTRB + kb + qq * 4);
                    uint32_t b1 = *reinterpret_cast<const uint32_t*>(
                        smw + (size_t)o * WSTRB + kb + 16 + qq * 4);
                    mma16816(c[nt][0], c[nt][1], c[nt][2], c[nt][3],
                             a0, a1, a2, a3, b0, b1);
                }
            }
            float* pw = part + (size_t)warp * PARTW;
#pragma unroll
            for (int nt = 0; nt < 4; nt++) {
                *reinterpret_cast<float2*>(pw + gq * OSTR + nt * 8 + qq * 2) =
                    make_float2(c[nt][0], c[nt][1]);
                *reinterpret_cast<float2*>(pw + (gq + 8) * OSTR + nt * 8 + qq * 2) =
                    make_float2(c[nt][2], c[nt][3]);
            }
        }
        __syncthreads();

        // ================= Phase 3: reduce + bias, store ====================
        {
            float s = __ldg(bias + lane);
#pragma unroll
            for (int w2 = 0; w2 < 16; w2++)
                s += part[(size_t)w2 * PARTW + warp * OSTR + lane];
            out[((size_t)b * NPERB + n) * 32 + lane] = s;
        }
        __syncthreads();  // protect part/fs before next group
    }
}

// ---------------------------------------------------------------------------
extern "C" void kernel_launch(void* const* d_in, const int* in_sizes, int n_in,
                              void* d_out, int out_size) {
    const float* vox   = (const float*)d_in[0];   // (2,32,96,96,96)
    const float* verts = (const float*)d_in[1];   // (2,30000,3)
    const float* Wg    = (const float*)d_in[2];   // (32,32,1,27)
    const float* bias  = (const float*)d_in[3];   // (32,)
    float* out = (float*)d_out;

    __half* vt = nullptr;
    cudaGetSymbolAddress((void**)&vt, g_vt);

    cudaFuncSetAttribute(fused_kernel,
                         cudaFuncAttributeMaxDynamicSharedMemorySize, SMEM_BYTES);

    transpose_kernel<<<dim3(PVOX / 256, NB), 256>>>(vox, vt);
    fused_kernel<<<152, 512, SMEM_BYTES>>>(vt, verts, Wg, bias, out);
}

// round 8
// speedup vs baseline: 3.6880x; 1.2250x over previous
#include <cuda_runtime.h>
#include <cuda_fp16.h>
#include <cstdint>

// ---------------- problem constants ----------------
#define DIMV   96
#define PVOX   (96*96*96)            // 884736 positions
#define CCH    32
#define NB     2
#define NPERB  30000
#define NVTOT  60000
#define VPB    16                    // vertices per group (= warps per block)
#define NGROUPS (NVTOT/VPB)          // 3750
#define NSM    152
#define ITOT   864                   // C*27 reduction length

// smem layout (bytes)
#define WSTRB  2064                  // W row stride (fp16, k contiguous) ==16 mod 128
#define FSTRB  2064                  // feats row stride
#define WH_BYTES  (32*WSTRB)         // 66048
#define STG_ROW   256                // staging row: 4 positions x 64B
#define STG_V     (16*STG_ROW)       // 4096 per vertex
#define STG_BYTES (VPB*STG_V)        // 65536
#define FS_BYTES  (VPB*FSTRB)        // 33024
#define OSTR   36                    // part row stride (floats)
#define PARTW  (16*OSTR)             // floats per warp slab
#define PART_BYTES (16*PARTW*4)      // 36864
#define OFF_W    0
#define OFF_STG  (OFF_W + WH_BYTES)
#define OFF_FS   (OFF_STG + STG_BYTES)
#define OFF_PART (OFF_FS + FS_BYTES)
#define SMEM_BYTES (OFF_PART + PART_BYTES)   // 201472

// Scratch: transposed voxel features (B,H,W,D,C) fp16 (113 MB -> L2-resident)
__device__ __half g_vt[(size_t)NB * PVOX * CCH];

static __device__ __forceinline__ uint32_t smem_u32(const void* p) {
    uint32_t a;
    asm("{ .reg .u64 t; cvta.to.shared.u64 t, %1; cvt.u32.u64 %0, t; }" : "=r"(a) : "l"(p));
    return a;
}
static __device__ __forceinline__ void cp_async16(uint32_t dst, const void* src) {
    asm volatile("cp.async.cg.shared.global [%0], [%1], 16;" :: "r"(dst), "l"(src));
}
static __device__ __forceinline__ void cp_commit() {
    asm volatile("cp.async.commit_group;");
}
static __device__ __forceinline__ void cp_wait0() {
    asm volatile("cp.async.wait_group 0;");
}

// warp MMA m16n8k16 f16 x f16 -> f32
static __device__ __forceinline__ void mma16816(
    float& c0, float& c1, float& c2, float& c3,
    uint32_t a0, uint32_t a1, uint32_t a2, uint32_t a3,
    uint32_t b0, uint32_t b1) {
    asm volatile(
        "mma.sync.aligned.m16n8k16.row.col.f32.f16.f16.f32 "
        "{%0,%1,%2,%3}, {%4,%5,%6,%7}, {%8,%9}, {%0,%1,%2,%3};"
        : "+f"(c0), "+f"(c1), "+f"(c2), "+f"(c3)
        : "r"(a0), "r"(a1), "r"(a2), "r"(a3), "r"(b0), "r"(b1));
}

// ---------------------------------------------------------------------------
// Kernel 1: transpose (B,C,P) fp32 -> (B,P,C) fp16, register transpose.
// ---------------------------------------------------------------------------
__global__ void __launch_bounds__(256) transpose_kernel(
    const float* __restrict__ in, __half* __restrict__ vt) {
    const int b    = blockIdx.y;
    const int warp = threadIdx.x >> 5;
    const int lane = threadIdx.x & 31;
    const int p0   = (blockIdx.x * 8 + warp) * 32;

    const float* ib = in + (size_t)b * CCH * PVOX + p0 + lane;
    __half2 h[16];
#pragma unroll
    for (int c = 0; c < 32; c += 2) {
        float v0 = __ldg(ib + (size_t)c * PVOX);
        float v1 = __ldg(ib + (size_t)(c + 1) * PVOX);
        h[c >> 1] = __floats2half2_rn(v0, v1);
    }
    uint4* ob = reinterpret_cast<uint4*>(vt + ((size_t)b * PVOX + p0 + lane) * CCH);
    const uint4* hs = reinterpret_cast<const uint4*>(h);
#pragma unroll
    for (int k = 0; k < 4; k++) ob[k] = hs[k];
}

// ---------------------------------------------------------------------------
// Kernel 2: persistent fused sample + conv, cp.async-pipelined gather.
//  Per group: wait staged gather -> interp (LDS) -> feats fp16; issue async
//  gather for group g+NSM; HMMA conv; cross-warp reduce. Staging slab is
//  warp-private (warp == vertex) so the async copies need no barriers.
// ---------------------------------------------------------------------------
__global__ void __launch_bounds__(512, 1) fused_kernel(
    const __half* __restrict__ vt,
    const float* __restrict__ verts,
    const float* __restrict__ Wg,      // (32,32,1,27): o*864 + c*27 + k
    const float* __restrict__ bias,
    float* __restrict__ out) {
    extern __shared__ char smc[];
    char*  smw  = smc + OFF_W;           // W fp16 [32][WSTRB]
    char*  smf  = smc + OFF_FS;          // feats fp16 [16][FSTRB]
    float* part = (float*)(smc + OFF_PART);

    const int tid  = threadIdx.x;
    const int warp = tid >> 5;
    const int lane = tid & 31;
    const uint32_t stgW = smem_u32(smc + OFF_STG) + warp * STG_V;

    // ---- one-time: stage W (fp16, o-major), zero K-pad; zero feats pad ----
    for (int g = tid; g < 32 * (WSTRB / 4); g += 512) {
        int o = g / (WSTRB / 4);
        int w = g - o * (WSTRB / 4);
        int k0 = w * 2;
        __half2 hv = __floats2half2_rn(0.f, 0.f);
        if (k0 < ITOT) {
            float w0 = Wg[(size_t)o * ITOT + k0];
            float w1 = (k0 + 1 < ITOT) ? Wg[(size_t)o * ITOT + k0 + 1] : 0.f;
            hv = __floats2half2_rn(w0, w1);
        }
        *reinterpret_cast<uint32_t*>(smw + (size_t)o * WSTRB + w * 4) =
            *reinterpret_cast<uint32_t*>(&hv);
    }
    for (int g = tid; g < VPB * (FSTRB / 4 - ITOT / 2); g += 512) {
        int v = g / (FSTRB / 4 - ITOT / 2);
        int j = g - v * (FSTRB / 4 - ITOT / 2) + ITOT / 2;
        *reinterpret_cast<uint32_t*>(smf + (size_t)v * FSTRB + j * 4) = 0u;
    }
    __syncthreads();

    const int gq = lane >> 2;   // fragment row
    const int qq = lane & 3;    // fragment col group
    const int rsel = lane >> 4; // staging copy: which of 2 rows
    const int ln16 = lane & 15; // 16B chunk within row

    // persistent "staged group" coords (per warp's vertex)
    float sfx = 0.f, sfy = 0.f, sfz = 0.f;
    int ssx0 = 0, ssx1 = 0, ssx2 = 0, ssx3 = 0;

    // stage(): compute coords for group grp's vertex and issue async gather
    auto stage = [&](int grp) {
        const int vglob = grp * VPB + warp;
        const int b = vglob / NPERB;
        const float vx = verts[(size_t)vglob * 3 + 0];  // -> D axis (x)
        const float vy = verts[(size_t)vglob * 3 + 1];  // -> W axis (y)
        const float vz = verts[(size_t)vglob * 3 + 2];  // -> H axis (z)

        int xlo, cnt16;
        {
            float f = fminf(fmaxf((vx + 1.f) * 47.5f, 0.f), 95.f);
            int i0 = (int)f; sfx = f - (float)i0;
            xlo = max(i0 - 1, 0);
            int xhi = min(i0 + 2, 95);
            cnt16 = (xhi - xlo + 1) * 4;           // 16B chunks per row
            ssx0 = max(i0 - 1, 0) - xlo;
            ssx1 = i0 - xlo;
            ssx2 = min(i0 + 1, 95) - xlo;
            ssx3 = min(i0 + 2, 95) - xlo;
        }
        int yp[4], zp[4];
        {
            float f = fminf(fmaxf((vy + 1.f) * 47.5f, 0.f), 95.f);
            int i0 = (int)f; sfy = f - (float)i0;
#pragma unroll
            for (int j = 0; j < 4; j++) yp[j] = min(max(i0 - 1 + j, 0), 95);
        }
        {
            float f = fminf(fmaxf((vz + 1.f) * 47.5f, 0.f), 95.f);
            int i0 = (int)f; sfz = f - (float)i0;
#pragma unroll
            for (int j = 0; j < 4; j++) zp[j] = min(max(i0 - 1 + j, 0), 95);
        }
        const char* vb = (const char*)(vt + ((size_t)b * PVOX) * CCH);
        const bool on = (ln16 < cnt16);
#pragma unroll
        for (int step = 0; step < 8; step++) {
            int row = step * 2 + rsel;
            int jz = row >> 2, jy = row & 3;
            size_t pos = ((size_t)zp[jz] * (DIMV * DIMV) + (size_t)yp[jy] * DIMV + xlo);
            const char* src = vb + pos * (CCH * 2) + ln16 * 16;
            uint32_t dst = stgW + row * STG_ROW + ln16 * 16;
            if (on) cp_async16(dst, src);
        }
        cp_commit();
    };

    // prologue: stage first group
    stage(blockIdx.x);

    for (int grp = blockIdx.x; grp < NGROUPS; grp += NSM) {
        // snapshot staged coords (stage() below overwrites them)
        const float fx = sfx, fy = sfy, fz = sfz;
        const int sx[4] = {ssx0, ssx1, ssx2, ssx3};
        const int vglob = grp * VPB + warp;
        const int b = vglob / NPERB;
        const int n = vglob - b * NPERB;

        cp_wait0();   // my staged rows are in smem (warp-private)

        // ================= interp from staging -> feats fp16 ================
        {
            const float omfz = 1.f - fz;
            float acc[27];
#pragma unroll
            for (int kk = 0; kk < 27; kk++) acc[kk] = 0.f;

            const __half* stg = reinterpret_cast<const __half*>(
                smc + OFF_STG + warp * STG_V);
#pragma unroll
            for (int jz = 0; jz < 4; jz++) {
                float t4[12];
#pragma unroll
                for (int jy = 0; jy < 4; jy++) {
                    const __half* r = stg + ((jz * 4 + jy) * STG_ROW) / 2 + lane;
                    float a0 = __half2float(r[sx[0] * 32]);
                    float a1 = __half2float(r[sx[1] * 32]);
                    float a2 = __half2float(r[sx[2] * 32]);
                    float a3 = __half2float(r[sx[3] * 32]);
                    t4[jy * 3 + 0] = a0 + fx * (a1 - a0);
                    t4[jy * 3 + 1] = a1 + fx * (a2 - a1);
                    t4[jy * 3 + 2] = a2 + fx * (a3 - a2);
                }
#pragma unroll
                for (int dy = 0; dy < 3; dy++) {
#pragma unroll
                    for (int dxx = 0; dxx < 3; dxx++) {
                        float a  = t4[dy * 3 + dxx];
                        float bq = t4[(dy + 1) * 3 + dxx];
                        float ly = a + fy * (bq - a);
                        if (jz < 3) acc[dxx * 9 + dy * 3 + jz]       += omfz * ly;
                        if (jz > 0) acc[dxx * 9 + dy * 3 + (jz - 1)] += fz   * ly;
                    }
                }
            }
            __half* fr = reinterpret_cast<__half*>(smf + (size_t)warp * FSTRB) + lane * 27;
#pragma unroll
            for (int kk = 0; kk < 27; kk++) fr[kk] = __float2half_rn(acc[kk]);
        }

        // issue async gather for the next group (overwrites own stage slab —
        // safe: this warp finished reading it above)
        const int nxt = grp + NSM;
        if (nxt < NGROUPS) stage(nxt);

        __syncthreads();   // feats of all warps visible

        // ================= HMMA conv ========================================
        {
            float c[4][4];
#pragma unroll
            for (int nt = 0; nt < 4; nt++)
#pragma unroll
                for (int r = 0; r < 4; r++) c[nt][r] = 0.f;

#pragma unroll
            for (int t = 0; t < 4; t++) {
                const int kb = (warp * 4 + t) * 32;
                uint32_t a0 = *reinterpret_cast<const uint32_t*>(
                    smf + (size_t)gq * FSTRB + kb + qq * 4);
                uint32_t a1 = *reinterpret_cast<const uint32_t*>(
                    smf + (size_t)(gq + 8) * FSTRB + kb + qq * 4);
                uint32_t a2 = *reinterpret_cast<const uint32_t*>(
                    smf + (size_t)gq * FSTRB + kb + 16 + qq * 4);
                uint32_t a3 = *reinterpret_cast<const uint32_t*>(
                    smf + (size_t)(gq + 8) * FSTRB + kb + 16 + qq * 4);
#pragma unroll
                for (int nt = 0; nt < 4; nt++) {
                    const int o = nt * 8 + gq;
                    uint32_t b0 = *reinterpret_cast<const uint32_t*>(
                        smw + (size_t)o * WSTRB + kb + qq * 4);
                    uint32_t b1 = *reinterpret_cast<const uint32_t*>(
                        smw + (size_t)o * WSTRB + kb + 16 + qq * 4);
                    mma16816(c[nt][0], c[nt][1], c[nt][2], c[nt][3],
                             a0, a1, a2, a3, b0, b1);
                }
            }
            float* pw = part + (size_t)warp * PARTW;
#pragma unroll
            for (int nt = 0; nt < 4; nt++) {
                *reinterpret_cast<float2*>(pw + gq * OSTR + nt * 8 + qq * 2) =
                    make_float2(c[nt][0], c[nt][1]);
                *reinterpret_cast<float2*>(pw + (gq + 8) * OSTR + nt * 8 + qq * 2) =
                    make_float2(c[nt][2], c[nt][3]);
            }
        }
        __syncthreads();   // part visible

        // ================= reduce + bias, store =============================
        {
            float s = __ldg(bias + lane);
#pragma unroll
            for (int w2 = 0; w2 < 16; w2++)
                s += part[(size_t)w2 * PARTW + warp * OSTR + lane];
            out[((size_t)b * NPERB + n) * 32 + lane] = s;
        }
        __syncthreads();   // part/feats consumed before next group overwrites
    }
}

// ---------------------------------------------------------------------------
extern "C" void kernel_launch(void* const* d_in, const int* in_sizes, int n_in,
                              void* d_out, int out_size) {
    const float* vox   = (const float*)d_in[0];   // (2,32,96,96,96)
    const float* verts = (const float*)d_in[1];   // (2,30000,3)
    const float* Wg    = (const float*)d_in[2];   // (32,32,1,27)
    const float* bias  = (const float*)d_in[3];   // (32,)
    float* out = (float*)d_out;

    __half* vt = nullptr;
    cudaGetSymbolAddress((void**)&vt, g_vt);

    cudaFuncSetAttribute(fused_kernel,
                         cudaFuncAttributeMaxDynamicSharedMemorySize, SMEM_BYTES);

    transpose_kernel<<<dim3(PVOX / 256, NB), 256>>>(vox, vt);
    fused_kernel<<<NSM, 512, SMEM_BYTES>>>(vt, verts, Wg, bias, out);
}